// round 10
// baseline (speedup 1.0000x reference)
#include <cuda_runtime.h>
#include <cuda_bf16.h>

// Bilinear grid sampler: B=16, H=256, W=256, C=64, fp32.
// U [B,H,W,C], grid [B,H,W,2], out [B,H,W,C].
// 16 threads per pixel, one float4 per thread (256B coalesced per corner).
// 4 ADJACENT pixels per thread (L2 locality), block=128, volatile front-
// batched loads + __syncwarp + streaming stores (round-9 best = 94.2us).
// This round: U loads switch .nc -> .cg (cache at L2 only) INSIDE the
// volatile asm, isolating the cache policy from the reg/occupancy confound
// that sank round 8 (intrinsic __ldcg let ptxas reschedule: regs 40, occ 64%).
// Gather lines have ~0 same-SM L1 reuse (random coords, 148 SMs) -> L1
// allocation is pure fill overhead; their 4x reuse lives in L2.

#define BS_B 16
#define BS_H 256
#define BS_W 256
#define BS_PIX (BS_B * BS_H * BS_W)     // 1,048,576
#define NPIX 4

__device__ __forceinline__ float4 ldg_v4_cg_volatile(const float4* p)
{
    float4 v;
    asm volatile("ld.global.cg.v4.f32 {%0,%1,%2,%3}, [%4];"
                 : "=f"(v.x), "=f"(v.y), "=f"(v.z), "=f"(v.w)
                 : "l"(p));
    return v;
}

__device__ __forceinline__ void pixel_setup(const float gx, const float gy,
                                            int b, int lane,
                                            int& ia, int& ib, int& ic, int& id,
                                            float& wa, float& wb, float& wc, float& wd)
{
    const float x = 0.5f * (gx + 1.0f) * (float)(BS_W - 1);
    const float y = 0.5f * (gy + 1.0f) * (float)(BS_H - 1);

    const int x0 = (int)floorf(x);
    const int y0 = (int)floorf(y);

    const int x0c = min(max(x0, 0), BS_W - 1);
    const int x1c = min(max(x0 + 1, 0), BS_W - 1);
    const int y0c = min(max(y0, 0), BS_H - 1);
    const int y1c = min(max(y0 + 1, 0), BS_H - 1);

    const float x0f = (float)x0c, x1f = (float)x1c;
    const float y0f = (float)y0c, y1f = (float)y1c;

    wa = (x1f - x) * (y1f - y);
    wb = (x1f - x) * (y - y0f);
    wc = (x - x0f) * (y1f - y);
    wd = (x - x0f) * (y - y0f);

    // float4 index space: [B, H, W, 16]
    const int base = b << 16;                       // b * H * W
    const int r0 = (base + (y0c << 8)) << 4;
    const int r1 = (base + (y1c << 8)) << 4;
    const int xo0 = (x0c << 4) + lane;
    const int xo1 = (x1c << 4) + lane;
    ia = r0 + xo0;
    ib = r1 + xo0;
    ic = r0 + xo1;
    id = r1 + xo1;
}

__global__ __launch_bounds__(128)
void bilinear_sampler_kernel(const float* __restrict__ U,
                             const float* __restrict__ grid,
                             float* __restrict__ out)
{
    const int t    = blockIdx.x * 128 + threadIdx.x;
    const int lane = t & 15;
    const int g    = t >> 4;                 // 0 .. BS_PIX/4 - 1
    const int pixbase = g << 2;              // 4 adjacent pixels, same batch
    const int b = pixbase >> 16;

    const float4* __restrict__ grid4 = (const float4*)grid;
    const float4* __restrict__ U4    = (const float4*)U;
    float4* __restrict__ out4        = (float4*)out;

    // 4 pixels' coords = 32 contiguous bytes = 2 x float4 (L1 broadcast)
    const float4 gc01 = __ldg(grid4 + (g << 1));
    const float4 gc23 = __ldg(grid4 + (g << 1) + 1);
    const float gx[NPIX] = {gc01.x, gc01.z, gc23.x, gc23.z};
    const float gy[NPIX] = {gc01.y, gc01.w, gc23.y, gc23.w};

    int ia[NPIX], ib[NPIX], ic[NPIX], id[NPIX];
    float wa[NPIX], wb[NPIX], wc[NPIX], wd[NPIX];

#pragma unroll
    for (int k = 0; k < NPIX; k++) {
        pixel_setup(gx[k], gy[k], b, lane,
                    ia[k], ib[k], ic[k], id[k],
                    wa[k], wb[k], wc[k], wd[k]);
    }

    // 16 independent loads, all issued before the fence; L2-only caching
    float4 A[NPIX], Bv[NPIX], Cv[NPIX], D[NPIX];
#pragma unroll
    for (int k = 0; k < NPIX; k++) {
        A[k]  = ldg_v4_cg_volatile(U4 + ia[k]);
        Bv[k] = ldg_v4_cg_volatile(U4 + ib[k]);
        Cv[k] = ldg_v4_cg_volatile(U4 + ic[k]);
        D[k]  = ldg_v4_cg_volatile(U4 + id[k]);
    }

    __syncwarp();   // consumers cannot hoist above; loads cannot sink below

#pragma unroll
    for (int k = 0; k < NPIX; k++) {
        float4 r;
        r.x = wa[k] * A[k].x + wb[k] * Bv[k].x + wc[k] * Cv[k].x + wd[k] * D[k].x;
        r.y = wa[k] * A[k].y + wb[k] * Bv[k].y + wc[k] * Cv[k].y + wd[k] * D[k].y;
        r.z = wa[k] * A[k].z + wb[k] * Bv[k].z + wc[k] * Cv[k].z + wd[k] * D[k].z;
        r.w = wa[k] * A[k].w + wb[k] * Bv[k].w + wc[k] * Cv[k].w + wd[k] * D[k].w;
        __stcs(&out4[((pixbase + k) << 4) + lane], r);   // streaming store
    }
}

extern "C" void kernel_launch(void* const* d_in, const int* in_sizes, int n_in,
                              void* d_out, int out_size)
{
    const float* U    = (const float*)d_in[0];
    const float* grid = (const float*)d_in[1];
    float* out        = (float*)d_out;

    // (BS_PIX/4) pixel-quads * 16 lanes = 4,194,304 threads
    const int block = 128;
    const int gridsz = (BS_PIX / 4 * 16) / block;   // 32768
    bilinear_sampler_kernel<<<gridsz, block>>>(U, grid, out);
}

// round 11
// speedup vs baseline: 1.0480x; 1.0480x over previous
#include <cuda_runtime.h>
#include <cuda_bf16.h>

// Bilinear grid sampler: B=16, H=256, W=256, C=64, fp32.
// U [B,H,W,C], grid [B,H,W,2], out [B,H,W,C].
// 16 threads per pixel, one float4 per thread (256B coalesced per corner).
// 4 ADJACENT pixels per thread (L2 locality). Volatile .nc front-batched
// loads + __syncwarp + streaming stores (round-9 best config, 94.2us).
// Round-10 falsified .cg (costs +8 regs -> occ 66% -> 98.5us); reverted.
// This round continues the only knob with a measured positive derivative:
// CTA granularity (256->128 gave -0.7us). block 128 -> 64 for finer wave
// balance and shallower per-CTA bursts into the L1tex wavefront queue.

#define BS_B 16
#define BS_H 256
#define BS_W 256
#define BS_PIX (BS_B * BS_H * BS_W)     // 1,048,576
#define NPIX 4

__device__ __forceinline__ float4 ldg_v4_volatile(const float4* p)
{
    float4 v;
    asm volatile("ld.global.nc.v4.f32 {%0,%1,%2,%3}, [%4];"
                 : "=f"(v.x), "=f"(v.y), "=f"(v.z), "=f"(v.w)
                 : "l"(p));
    return v;
}

__device__ __forceinline__ void pixel_setup(const float gx, const float gy,
                                            int b, int lane,
                                            int& ia, int& ib, int& ic, int& id,
                                            float& wa, float& wb, float& wc, float& wd)
{
    const float x = 0.5f * (gx + 1.0f) * (float)(BS_W - 1);
    const float y = 0.5f * (gy + 1.0f) * (float)(BS_H - 1);

    const int x0 = (int)floorf(x);
    const int y0 = (int)floorf(y);

    const int x0c = min(max(x0, 0), BS_W - 1);
    const int x1c = min(max(x0 + 1, 0), BS_W - 1);
    const int y0c = min(max(y0, 0), BS_H - 1);
    const int y1c = min(max(y0 + 1, 0), BS_H - 1);

    const float x0f = (float)x0c, x1f = (float)x1c;
    const float y0f = (float)y0c, y1f = (float)y1c;

    wa = (x1f - x) * (y1f - y);
    wb = (x1f - x) * (y - y0f);
    wc = (x - x0f) * (y1f - y);
    wd = (x - x0f) * (y - y0f);

    // float4 index space: [B, H, W, 16]
    const int base = b << 16;                       // b * H * W
    const int r0 = (base + (y0c << 8)) << 4;
    const int r1 = (base + (y1c << 8)) << 4;
    const int xo0 = (x0c << 4) + lane;
    const int xo1 = (x1c << 4) + lane;
    ia = r0 + xo0;
    ib = r1 + xo0;
    ic = r0 + xo1;
    id = r1 + xo1;
}

__global__ __launch_bounds__(64)
void bilinear_sampler_kernel(const float* __restrict__ U,
                             const float* __restrict__ grid,
                             float* __restrict__ out)
{
    const int t    = blockIdx.x * 64 + threadIdx.x;
    const int lane = t & 15;
    const int g    = t >> 4;                 // 0 .. BS_PIX/4 - 1
    const int pixbase = g << 2;              // 4 adjacent pixels, same batch
    const int b = pixbase >> 16;

    const float4* __restrict__ grid4 = (const float4*)grid;
    const float4* __restrict__ U4    = (const float4*)U;
    float4* __restrict__ out4        = (float4*)out;

    // 4 pixels' coords = 32 contiguous bytes = 2 x float4 (L1 broadcast)
    const float4 gc01 = __ldg(grid4 + (g << 1));
    const float4 gc23 = __ldg(grid4 + (g << 1) + 1);
    const float gx[NPIX] = {gc01.x, gc01.z, gc23.x, gc23.z};
    const float gy[NPIX] = {gc01.y, gc01.w, gc23.y, gc23.w};

    int ia[NPIX], ib[NPIX], ic[NPIX], id[NPIX];
    float wa[NPIX], wb[NPIX], wc[NPIX], wd[NPIX];

#pragma unroll
    for (int k = 0; k < NPIX; k++) {
        pixel_setup(gx[k], gy[k], b, lane,
                    ia[k], ib[k], ic[k], id[k],
                    wa[k], wb[k], wc[k], wd[k]);
    }

    // 16 independent loads, all issued before the fence
    float4 A[NPIX], Bv[NPIX], Cv[NPIX], D[NPIX];
#pragma unroll
    for (int k = 0; k < NPIX; k++) {
        A[k]  = ldg_v4_volatile(U4 + ia[k]);
        Bv[k] = ldg_v4_volatile(U4 + ib[k]);
        Cv[k] = ldg_v4_volatile(U4 + ic[k]);
        D[k]  = ldg_v4_volatile(U4 + id[k]);
    }

    __syncwarp();   // consumers cannot hoist above; loads cannot sink below

#pragma unroll
    for (int k = 0; k < NPIX; k++) {
        float4 r;
        r.x = wa[k] * A[k].x + wb[k] * Bv[k].x + wc[k] * Cv[k].x + wd[k] * D[k].x;
        r.y = wa[k] * A[k].y + wb[k] * Bv[k].y + wc[k] * Cv[k].y + wd[k] * D[k].y;
        r.z = wa[k] * A[k].z + wb[k] * Bv[k].z + wc[k] * Cv[k].z + wd[k] * D[k].z;
        r.w = wa[k] * A[k].w + wb[k] * Bv[k].w + wc[k] * Cv[k].w + wd[k] * D[k].w;
        __stcs(&out4[((pixbase + k) << 4) + lane], r);   // streaming store
    }
}

extern "C" void kernel_launch(void* const* d_in, const int* in_sizes, int n_in,
                              void* d_out, int out_size)
{
    const float* U    = (const float*)d_in[0];
    const float* grid = (const float*)d_in[1];
    float* out        = (float*)d_out;

    // (BS_PIX/4) pixel-quads * 16 lanes = 4,194,304 threads
    const int block = 64;
    const int gridsz = (BS_PIX / 4 * 16) / block;   // 65536
    bilinear_sampler_kernel<<<gridsz, block>>>(U, grid, out);
}